// round 5
// baseline (speedup 1.0000x reference)
#include <cuda_runtime.h>
#include <math.h>
#include <stdint.h>

// Problem constants
#define T_DIM 2048
#define B_DIM 1024
#define A_DIM 4
#define D_DIM 128
#define P_DIM 256

constexpr int CHUNK  = 32;               // timesteps per tile (rows = 32*4 = 128)
constexpr int NCHUNK = T_DIM / CHUNK;    // 64
constexpr int SROW   = 132;              // padded SMEM row stride (floats)

// Output layout: [logits (T,1,B,A)] [q (B,A,D)] [h (B,A,D)]
constexpr int OUT_Q = T_DIM * B_DIM * A_DIM;          // 8388608
constexpr int OUT_H = OUT_Q + B_DIM * A_DIM * D_DIM;  // 8912896

// SMEM layout (float offsets)
constexpr int SM_B     = 0;                   // C^T tf32-rounded: sB[e*SROW + d] = C[d][e]
constexpr int SM_A     = SM_B + 128 * SROW;   // H tile fp32: sA[r*SROW + d]
constexpr int SM_Q     = SM_A + 128 * SROW;   // Q tile fp32
constexpr int SM_PHI   = SM_Q + 128 * SROW;
constexpr int SM_OMPHI = SM_PHI + 128;
constexpr int SM_CHI   = SM_OMPHI + 128;
constexpr int SM_OMCHI = SM_CHI + 128;
constexpr int SM_BETA  = SM_OMCHI + 128;
constexpr int SM_KAPPA = SM_BETA + 128;
constexpr int SM_INP   = SM_KAPPA + 128;      // 32 t x 8 (act[4], rew[4])
constexpr int SM_LOG   = SM_INP + 256;        // 128 per-row bilinear+beta sums
constexpr int SM_KH    = SM_LOG + 128;        // 128 kappa.h sums
constexpr int SM_TOT   = SM_KH + 128;
constexpr int SMEM_BYTES = SM_TOT * 4;        // 207,872 bytes

__device__ __forceinline__ uint32_t f2tf(float x) {
    uint32_t u;
    asm("cvt.rna.tf32.f32 %0, %1;" : "=r"(u) : "f"(x));
    return u;
}

__device__ __forceinline__ void mma_tf32(float* c, const uint32_t* a, const uint32_t* b) {
    asm volatile(
        "mma.sync.aligned.m16n8k8.row.col.f32.tf32.tf32.f32 "
        "{%0,%1,%2,%3}, {%4,%5,%6,%7}, {%8,%9}, {%0,%1,%2,%3};\n"
        : "+f"(c[0]), "+f"(c[1]), "+f"(c[2]), "+f"(c[3])
        : "r"(a[0]), "r"(a[1]), "r"(a[2]), "r"(a[3]),
          "r"(b[0]), "r"(b[1]));
}

__global__ __launch_bounds__(256, 1)
void gql_kernel(const float* __restrict__ inp,       // (T,1,B,9)
                const float* __restrict__ phi_raw,   // (P,D)
                const float* __restrict__ chi_raw,
                const float* __restrict__ beta_raw,
                const float* __restrict__ kap_raw,
                const float* __restrict__ C_raw,     // (P,D,D)
                float* __restrict__ out)
{
    extern __shared__ float sm[];
    const int b    = blockIdx.x;
    const int tid  = threadIdx.x;
    const int lane = tid & 31;
    const int warp = tid >> 5;

    // participant id from t=0 row
    const int pid = (int)inp[b * 9 + 8];

    // ---------------- one-time parameter setup ----------------
    if (tid < 128) {
        const int d = tid;
        float pv = phi_raw[pid * 128 + d];
        float ph = 1.0f / (1.0f + expf(-pv));
        ph = fminf(fmaxf(ph, 0.01f), 0.99f);
        sm[SM_PHI + d]   = ph;
        sm[SM_OMPHI + d] = 1.0f - ph;

        float cv = chi_raw[pid * 128 + d];
        float ch = 1.0f / (1.0f + expf(-cv));
        ch = fminf(fmaxf(ch, 0.01f), 0.99f);
        sm[SM_CHI + d]   = ch;
        sm[SM_OMCHI + d] = 1.0f - ch;

        float bv = beta_raw[pid * 128 + d];
        float sp = (bv > 15.0f) ? bv : log1pf(expf(bv));
        sm[SM_BETA + d] = fminf(fmaxf(sp, 0.1f), 10.0f);

        float kv = kap_raw[pid * 128 + d];
        sm[SM_KAPPA + d] = fminf(fmaxf(kv, -10.0f), 10.0f);
    }

    // C[pid] : clip, tf32-round, store transposed (col-major B operand)
    {
        const float* Cb = C_raw + (size_t)pid * (128 * 128);
        for (int i = tid; i < 128 * 128; i += 256) {
            int d = i >> 7, e = i & 127;
            float v = fminf(fmaxf(Cb[i], -10.0f), 10.0f);
            sm[SM_B + e * SROW + d] = __uint_as_float(f2tf(v));
        }
    }
    __syncthreads();

    // ---------------- register-resident state ----------------
    // thread owns elements e0, e0+1 of flat (a,d) index; same a, consecutive d.
    const int e0    = tid * 2;
    const int a_own = e0 >> 7;
    const int d0    = e0 & 127;

    const float phi0 = sm[SM_PHI + d0],     phi1 = sm[SM_PHI + d0 + 1];
    const float omp0 = sm[SM_OMPHI + d0],   omp1 = sm[SM_OMPHI + d0 + 1];
    const float chi0 = sm[SM_CHI + d0],     chi1 = sm[SM_CHI + d0 + 1];
    const float omc0 = sm[SM_OMCHI + d0],   omc1 = sm[SM_OMCHI + d0 + 1];

    float q0 = 0.5f, q1 = 0.5f, h0 = 0.0f, h1 = 0.0f;

    const int wm  = warp >> 1;   // 0..3  (M tile of 32 rows)
    const int wn  = warp & 1;    // 0..1  (N tile of 64 cols)
    const int grp = lane >> 2;   // 0..7
    const int qd  = lane & 3;    // 0..3

    for (int c = 0; c < NCHUNK; c++) {
        const int tb = c * CHUNK;

        // ---- stage 1: zero row sums, load this chunk's inputs ----
        if (tid < 128) sm[SM_LOG + tid] = 0.0f;
        {
            int t = tid >> 3, cc = tid & 7;
            float v = inp[((size_t)(tb + t) * B_DIM + b) * 9 + cc];
            if (v != v) v = 0.0f;   // nan_to_num
            sm[SM_INP + tid] = v;
        }
        __syncthreads();

        // ---- stage 2: EMA scan, write H/Q tiles ----
#pragma unroll 8
        for (int t = 0; t < CHUNK; t++) {
            float av = sm[SM_INP + t * 8 + a_own];
            float rv = sm[SM_INP + t * 8 + 4 + a_own];
            float drive = rv * av;
            q0 = fmaf(phi0, drive, omp0 * q0);
            q1 = fmaf(phi1, drive, omp1 * q1);
            h0 = fmaf(chi0, av, omc0 * h0);
            h1 = fmaf(chi1, av, omc1 * h1);
            int row = t * 4 + a_own;
            *(float2*)&sm[SM_A + row * SROW + d0] = make_float2(h0, h1);
            *(float2*)&sm[SM_Q + row * SROW + d0] = make_float2(q0, q1);
        }
        __syncthreads();

        // ---- stage 3: P = H * C  (tf32 mma), warp tile 32x64 ----
        float acc[2][8][4];
#pragma unroll
        for (int i = 0; i < 2; i++)
#pragma unroll
            for (int j = 0; j < 8; j++)
#pragma unroll
                for (int r = 0; r < 4; r++) acc[i][j][r] = 0.0f;

        for (int k0 = 0; k0 < 128; k0 += 8) {
            uint32_t af[2][4];
#pragma unroll
            for (int i = 0; i < 2; i++) {
                const float* base = &sm[SM_A + (wm * 32 + i * 16 + grp) * SROW + k0 + qd];
                af[i][0] = f2tf(base[0]);
                af[i][1] = f2tf(base[8 * SROW]);
                af[i][2] = f2tf(base[4]);
                af[i][3] = f2tf(base[8 * SROW + 4]);
            }
            uint32_t bf[8][2];
#pragma unroll
            for (int j = 0; j < 8; j++) {
                const float* base = &sm[SM_B + (wn * 64 + j * 8 + grp) * SROW + k0 + qd];
                bf[j][0] = __float_as_uint(base[0]);
                bf[j][1] = __float_as_uint(base[4]);
            }
#pragma unroll
            for (int i = 0; i < 2; i++)
#pragma unroll
                for (int j = 0; j < 8; j++)
                    mma_tf32(acc[i][j], af[i], bf[j]);
        }

        // ---- kappa . h (fp32, float4) ----
        if (tid < 128) {
            float kh = 0.0f;
            const float4* hv = (const float4*)&sm[SM_A + tid * SROW];
            const float4* kv = (const float4*)&sm[SM_KAPPA];
#pragma unroll 8
            for (int d = 0; d < 32; d++) {
                float4 hh = hv[d], kk = kv[d];
                kh += hh.x * kk.x + hh.y * kk.y + hh.z * kk.z + hh.w * kk.w;
            }
            sm[SM_KH + tid] = kh;
        }

        // ---- epilogue: rowdot((P + 1*beta^T), Q) ----
#pragma unroll
        for (int i = 0; i < 2; i++) {
            float part0 = 0.0f, part1 = 0.0f;
            const int r0 = wm * 32 + i * 16 + grp;
            const int r1 = r0 + 8;
#pragma unroll
            for (int j = 0; j < 8; j++) {
                const int col = wn * 64 + j * 8 + qd * 2;
                const float b0 = sm[SM_BETA + col];
                const float b1 = sm[SM_BETA + col + 1];
                const float* q0p = &sm[SM_Q + r0 * SROW + col];
                const float* q1p = &sm[SM_Q + r1 * SROW + col];
                part0 += (acc[i][j][0] + b0) * q0p[0] + (acc[i][j][1] + b1) * q0p[1];
                part1 += (acc[i][j][2] + b0) * q1p[0] + (acc[i][j][3] + b1) * q1p[1];
            }
            part0 += __shfl_xor_sync(0xFFFFFFFFu, part0, 1);
            part0 += __shfl_xor_sync(0xFFFFFFFFu, part0, 2);
            part1 += __shfl_xor_sync(0xFFFFFFFFu, part1, 1);
            part1 += __shfl_xor_sync(0xFFFFFFFFu, part1, 2);
            if (qd == 0) {
                atomicAdd(&sm[SM_LOG + r0], part0);
                atomicAdd(&sm[SM_LOG + r1], part1);
            }
        }
        __syncthreads();

        // ---- write logits: shape (T,1,B,A) ----
        if (tid < 128) {
            int r = tid;
            int t = tb + (r >> 2);
            int a = r & 3;
            out[(size_t)t * (B_DIM * A_DIM) + b * A_DIM + a] = sm[SM_LOG + r] + sm[SM_KH + r];
        }
        __syncthreads();
    }

    // ---- final states: q (B,A,D) then h (B,A,D) ----
    *(float2*)&out[OUT_Q + (size_t)b * 512 + e0] = make_float2(q0, q1);
    *(float2*)&out[OUT_H + (size_t)b * 512 + e0] = make_float2(h0, h1);
}

extern "C" void kernel_launch(void* const* d_in, const int* in_sizes, int n_in,
                              void* d_out, int out_size) {
    const float* inp      = (const float*)d_in[0];
    const float* phi_raw  = (const float*)d_in[1];
    const float* chi_raw  = (const float*)d_in[2];
    const float* beta_raw = (const float*)d_in[3];
    const float* kap_raw  = (const float*)d_in[4];
    const float* C_raw    = (const float*)d_in[5];
    float* out = (float*)d_out;

    cudaFuncSetAttribute(gql_kernel, cudaFuncAttributeMaxDynamicSharedMemorySize, SMEM_BYTES);
    gql_kernel<<<B_DIM, 256, SMEM_BYTES>>>(inp, phi_raw, chi_raw, beta_raw, kap_raw, C_raw, out);
}

// round 7
// speedup vs baseline: 1.5861x; 1.5861x over previous
#include <cuda_runtime.h>
#include <math.h>
#include <stdint.h>

// Problem constants
#define T_DIM 2048
#define B_DIM 1024
#define A_DIM 4
#define D_DIM 128

constexpr int THREADS = 256;
constexpr int CHUNK   = 32;               // timesteps per tile -> 128 GEMM rows
constexpr int NCHUNK  = T_DIM / CHUNK;    // 64
constexpr int SROW    = 132;              // padded SMEM row stride (floats)

// Output layout: [logits (T,1,B,A)] [q (B,A,D)] [h (B,A,D)]
constexpr int OUT_Q = T_DIM * B_DIM * A_DIM;
constexpr int OUT_H = OUT_Q + B_DIM * A_DIM * D_DIM;

// SMEM layout (float offsets)
constexpr int SM_B     = 0;                   // C^T tf32: sB[e*SROW + d] = C[d][e]
constexpr int SM_A     = SM_B + 128 * SROW;   // H tile (tf32-rounded fp32 bits)
constexpr int SM_Q     = SM_A + 128 * SROW;   // Q tile fp32
constexpr int SM_PHI   = SM_Q + 128 * SROW;
constexpr int SM_OMPHI = SM_PHI + 128;
constexpr int SM_CHI   = SM_OMPHI + 128;
constexpr int SM_OMCHI = SM_CHI + 128;
constexpr int SM_BETA  = SM_OMCHI + 128;
constexpr int SM_KAPPA = SM_BETA + 128;
constexpr int SM_INP   = SM_KAPPA + 128;      // 32 t x 8 (act[4], rew[4])
constexpr int SM_PART  = SM_INP + 256;        // 4 col-groups x 128 rows
constexpr int SM_KH    = SM_PART + 512;       // 128 kappa.h sums
constexpr int SM_TOT   = SM_KH + 128;
constexpr int SMEM_BYTES = SM_TOT * 4;        // ~209 KB

__device__ __forceinline__ uint32_t f2tf(float x) {
    uint32_t u;
    asm("cvt.rna.tf32.f32 %0, %1;" : "=r"(u) : "f"(x));
    return u;
}

__device__ __forceinline__ void mma_tf32(float* c, const uint32_t* a, const uint32_t* b) {
    asm volatile(
        "mma.sync.aligned.m16n8k8.row.col.f32.tf32.tf32.f32 "
        "{%0,%1,%2,%3}, {%4,%5,%6,%7}, {%8,%9}, {%0,%1,%2,%3};\n"
        : "+f"(c[0]), "+f"(c[1]), "+f"(c[2]), "+f"(c[3])
        : "r"(a[0]), "r"(a[1]), "r"(a[2]), "r"(a[3]),
          "r"(b[0]), "r"(b[1]));
}

__global__ __launch_bounds__(THREADS, 1)
void gql_kernel(const float* __restrict__ inp,       // (T,1,B,9)
                const float* __restrict__ phi_raw,   // (P,D)
                const float* __restrict__ chi_raw,
                const float* __restrict__ beta_raw,
                const float* __restrict__ kap_raw,
                const float* __restrict__ C_raw,     // (P,D,D)
                float* __restrict__ out)
{
    extern __shared__ float sm[];
    const int b    = blockIdx.x;
    const int tid  = threadIdx.x;
    const int lane = tid & 31;
    const int warp = tid >> 5;

    const int pid = (int)inp[b * 9 + 8];

    // ---------------- one-time parameter setup ----------------
    if (tid < 128) {
        const int d = tid;
        float pv = phi_raw[pid * 128 + d];
        float ph = 1.0f / (1.0f + expf(-pv));
        ph = fminf(fmaxf(ph, 0.01f), 0.99f);
        sm[SM_PHI + d]   = ph;
        sm[SM_OMPHI + d] = 1.0f - ph;

        float cv = chi_raw[pid * 128 + d];
        float ch = 1.0f / (1.0f + expf(-cv));
        ch = fminf(fmaxf(ch, 0.01f), 0.99f);
        sm[SM_CHI + d]   = ch;
        sm[SM_OMCHI + d] = 1.0f - ch;

        float bv = beta_raw[pid * 128 + d];
        float sp = (bv > 15.0f) ? bv : log1pf(expf(bv));
        sm[SM_BETA + d] = fminf(fmaxf(sp, 0.1f), 10.0f);

        float kv = kap_raw[pid * 128 + d];
        sm[SM_KAPPA + d] = fminf(fmaxf(kv, -10.0f), 10.0f);
    }

    // C[pid]: clip, tf32-round, store transposed (col-major B operand)
    {
        const float* Cb = C_raw + (size_t)pid * (128 * 128);
        for (int i = tid; i < 128 * 128; i += THREADS) {
            int d = i >> 7, e = i & 127;
            float v = fminf(fmaxf(Cb[i], -10.0f), 10.0f);
            sm[SM_B + e * SROW + d] = __uint_as_float(f2tf(v));
        }
    }
    __syncthreads();

    // ---------------- per-thread scan state ----------------
    // thread owns flat (a,d) pair e0 = tid*2 (same a, consecutive d)
    const int e0    = tid * 2;
    const int a_own = e0 >> 7;
    const int d0    = e0 & 127;

    const float phi0 = sm[SM_PHI + d0],   phi1 = sm[SM_PHI + d0 + 1];
    const float omp0 = sm[SM_OMPHI + d0], omp1 = sm[SM_OMPHI + d0 + 1];
    const float chi0 = sm[SM_CHI + d0],   chi1 = sm[SM_CHI + d0 + 1];
    const float omc0 = sm[SM_OMCHI + d0], omc1 = sm[SM_OMCHI + d0 + 1];

    float q0 = 0.5f, q1 = 0.5f, h0 = 0.0f, h1 = 0.0f;

    // warp tile: 64 rows x 32 cols. wm in {0,1}, wn in {0..3}
    const int wm  = warp >> 2;
    const int wn  = warp & 3;
    const int grp = lane >> 2;   // 0..7
    const int qd  = lane & 3;    // 0..3

    // ---- hoist B fragments (C^T) into registers: invariant across chunks ----
    uint32_t bf[16][4][2];
#pragma unroll
    for (int k = 0; k < 16; k++) {
#pragma unroll
        for (int j = 0; j < 4; j++) {
            const float* base = &sm[SM_B + (wn * 32 + j * 8 + grp) * SROW + k * 8 + qd];
            bf[k][j][0] = __float_as_uint(base[0]);
            bf[k][j][1] = __float_as_uint(base[4]);
        }
    }

    for (int c = 0; c < NCHUNK; c++) {
        const int tb = c * CHUNK;

        // ---- stage 1: load chunk inputs ----
        {
            int t = tid >> 3, cc = tid & 7;
            float v = inp[((size_t)(tb + t) * B_DIM + b) * 9 + cc];
            if (v != v) v = 0.0f;   // nan_to_num
            sm[SM_INP + tid] = v;
        }
        __syncthreads();

        // ---- stage 2: EMA scan -> H (tf32-rounded) + Q (fp32) tiles ----
#pragma unroll 8
        for (int t = 0; t < CHUNK; t++) {
            float av = sm[SM_INP + t * 8 + a_own];
            float rv = sm[SM_INP + t * 8 + 4 + a_own];
            float drive = rv * av;
            q0 = fmaf(phi0, drive, omp0 * q0);
            q1 = fmaf(phi1, drive, omp1 * q1);
            h0 = fmaf(chi0, av, omc0 * h0);
            h1 = fmaf(chi1, av, omc1 * h1);
            int row = t * 4 + a_own;
            *(float2*)&sm[SM_A + row * SROW + d0] =
                make_float2(__uint_as_float(f2tf(h0)), __uint_as_float(f2tf(h1)));
            *(float2*)&sm[SM_Q + row * SROW + d0] = make_float2(q0, q1);
        }
        __syncthreads();

        // ---- stage 3: P = H * C  (tf32 mma), warp tile 64x32 ----
        float acc[4][4][4];
#pragma unroll
        for (int i = 0; i < 4; i++)
#pragma unroll
            for (int j = 0; j < 4; j++)
#pragma unroll
                for (int r = 0; r < 4; r++) acc[i][j][r] = 0.0f;

#pragma unroll
        for (int k = 0; k < 16; k++) {
            uint32_t af[4][4];
#pragma unroll
            for (int i = 0; i < 4; i++) {
                const float* base = &sm[SM_A + (wm * 64 + i * 16 + grp) * SROW + k * 8 + qd];
                af[i][0] = __float_as_uint(base[0]);
                af[i][1] = __float_as_uint(base[8 * SROW]);
                af[i][2] = __float_as_uint(base[4]);
                af[i][3] = __float_as_uint(base[8 * SROW + 4]);
            }
#pragma unroll
            for (int i = 0; i < 4; i++)
#pragma unroll
                for (int j = 0; j < 4; j++)
                    mma_tf32(acc[i][j], af[i], bf[k][j]);
        }

        // ---- kappa . h (reads tf32-rounded H; fp32 accumulate) ----
        if (tid < 128) {
            float kh = 0.0f;
            const float4* hv = (const float4*)&sm[SM_A + tid * SROW];
            const float4* kv = (const float4*)&sm[SM_KAPPA];
#pragma unroll 8
            for (int d = 0; d < 32; d++) {
                float4 hh = hv[d], kk = kv[d];
                kh += hh.x * kk.x + hh.y * kk.y + hh.z * kk.z + hh.w * kk.w;
            }
            sm[SM_KH + tid] = kh;
        }

        // ---- epilogue: rowdot((P + beta^T), Q) -> SM_PART[wn][row] ----
#pragma unroll
        for (int i = 0; i < 4; i++) {
            float part0 = 0.0f, part1 = 0.0f;
            const int r0 = wm * 64 + i * 16 + grp;
            const int r1 = r0 + 8;
#pragma unroll
            for (int j = 0; j < 4; j++) {
                const int col = wn * 32 + j * 8 + qd * 2;
                const float b0 = sm[SM_BETA + col];
                const float b1 = sm[SM_BETA + col + 1];
                const float* q0p = &sm[SM_Q + r0 * SROW + col];
                const float* q1p = &sm[SM_Q + r1 * SROW + col];
                part0 += (acc[i][j][0] + b0) * q0p[0] + (acc[i][j][1] + b1) * q0p[1];
                part1 += (acc[i][j][2] + b0) * q1p[0] + (acc[i][j][3] + b1) * q1p[1];
            }
            part0 += __shfl_xor_sync(0xFFFFFFFFu, part0, 1);
            part0 += __shfl_xor_sync(0xFFFFFFFFu, part0, 2);
            part1 += __shfl_xor_sync(0xFFFFFFFFu, part1, 1);
            part1 += __shfl_xor_sync(0xFFFFFFFFu, part1, 2);
            if (qd == 0) {
                sm[SM_PART + wn * 128 + r0] = part0;
                sm[SM_PART + wn * 128 + r1] = part1;
            }
        }
        __syncthreads();

        // ---- stage 5: combine col-groups + kappa.h, write logits (T,1,B,A) ----
        if (tid < 128) {
            float l = sm[SM_PART + tid] + sm[SM_PART + 128 + tid]
                    + sm[SM_PART + 256 + tid] + sm[SM_PART + 384 + tid]
                    + sm[SM_KH + tid];
            int t = tb + (tid >> 2);
            int a = tid & 3;
            out[(size_t)t * (B_DIM * A_DIM) + b * A_DIM + a] = l;
        }
        __syncthreads();
    }

    // ---- final states: q (B,A,D) then h (B,A,D) ----
    *(float2*)&out[OUT_Q + (size_t)b * 512 + e0] = make_float2(q0, q1);
    *(float2*)&out[OUT_H + (size_t)b * 512 + e0] = make_float2(h0, h1);
}

extern "C" void kernel_launch(void* const* d_in, const int* in_sizes, int n_in,
                              void* d_out, int out_size) {
    const float* inp      = (const float*)d_in[0];
    const float* phi_raw  = (const float*)d_in[1];
    const float* chi_raw  = (const float*)d_in[2];
    const float* beta_raw = (const float*)d_in[3];
    const float* kap_raw  = (const float*)d_in[4];
    const float* C_raw    = (const float*)d_in[5];
    float* out = (float*)d_out;

    cudaFuncSetAttribute(gql_kernel, cudaFuncAttributeMaxDynamicSharedMemorySize, SMEM_BYTES);
    gql_kernel<<<B_DIM, THREADS, SMEM_BYTES>>>(inp, phi_raw, chi_raw, beta_raw,
                                               kap_raw, C_raw, out);
}